// round 14
// baseline (speedup 1.0000x reference)
#include <cuda_runtime.h>
#include <cuda_fp16.h>
#include <math.h>
#include <stdint.h>

#define T 1024
#define C 128
#define NB 16
#define LUP 523776          // T*(T-1)/2
#define NOUT 2046           // LUP / 256
#define LEAK 0.2f

// ---------------------------------------------------------------------------
// Device globals (scratch)
// ---------------------------------------------------------------------------
__device__ __half g_up[(size_t)NB * LUP];  // packed upper-triangle distances (fp16)

// ---------------------------------------------------------------------------
// Helpers
// ---------------------------------------------------------------------------
__device__ __forceinline__ uint32_t to_tf32(float f) {
    uint32_t r;
    asm("cvt.rna.tf32.f32 %0, %1;" : "=r"(r) : "f"(f));
    return r;
}

__device__ __forceinline__ void mma_tf32(float* d, const uint32_t* a, const uint32_t* b) {
    asm volatile(
        "mma.sync.aligned.m16n8k8.row.col.f32.tf32.tf32.f32 "
        "{%0,%1,%2,%3}, {%4,%5,%6,%7}, {%8,%9}, {%0,%1,%2,%3};"
        : "+f"(d[0]), "+f"(d[1]), "+f"(d[2]), "+f"(d[3])
        : "r"(a[0]), "r"(a[1]), "r"(a[2]), "r"(a[3]),
          "r"(b[0]), "r"(b[1]));
}

__device__ __forceinline__ void mma_f16(float* d, const uint32_t* a, const uint32_t* b) {
    asm volatile(
        "mma.sync.aligned.m16n8k16.row.col.f32.f16.f16.f32 "
        "{%0,%1,%2,%3}, {%4,%5,%6,%7}, {%8,%9}, {%0,%1,%2,%3};"
        : "+f"(d[0]), "+f"(d[1]), "+f"(d[2]), "+f"(d[3])
        : "r"(a[0]), "r"(a[1]), "r"(a[2]), "r"(a[3]),
          "r"(b[0]), "r"(b[1]));
}

__device__ __forceinline__ float lrelu(float v) {
    return fmaxf(v, LEAK * v);
}

__device__ __forceinline__ float fsqrt_approx(float v) {
    float r;
    asm("sqrt.approx.f32 %0, %1;" : "=f"(r) : "f"(v));
    return r;
}

__device__ __forceinline__ uint32_t pack_h2(float x, float y) {
    __half2 h = __floats2half2_rn(x, y);
    return *(uint32_t*)&h;
}

// ---------------------------------------------------------------------------
// Kernel 1: tf32 mma.sync Gram tiles -> packed fp16 sqrt distances.
// (verbatim from the 94.6us round-13 build; xx fused in-block)
// ---------------------------------------------------------------------------
#define AS_STRIDE 132
#define AS_BYTES  (128 * AS_STRIDE * 4)       // 67584
#define DIST_SMEM (2 * AS_BYTES + 1024)       // + sxx[256]
#define HS_STRIDE 130

__global__ __launch_bounds__(256) void dist_kernel(const float* __restrict__ x) {
    extern __shared__ __align__(16) unsigned char sm[];
    uint32_t* As = (uint32_t*)sm;
    uint32_t* Bs = (uint32_t*)(sm + AS_BYTES);
    float* sxx   = (float*)(sm + 2 * AS_BYTES);

    int tid = threadIdx.x;
    int wid = tid >> 5;
    int lane = tid & 31;
    int grp = lane >> 2;
    int tg  = lane & 3;

    int b = blockIdx.y;
    int t = blockIdx.x;
    int ti = 0, rem = t;
    while (rem >= 8 - ti) { rem -= 8 - ti; ++ti; }
    int tj = ti + rem;
    int i0 = ti * 128, j0 = tj * 128;

    const float* xb = x + (size_t)b * T * C;

    #pragma unroll
    for (int it = 0; it < 16; ++it) {
        int f4 = it * 256 + tid;
        int row = f4 >> 5, c4 = f4 & 31;
        float4 va = *(const float4*)(xb + (size_t)(i0 + row) * C + c4 * 4);
        uint4 ta = make_uint4(to_tf32(va.x), to_tf32(va.y), to_tf32(va.z), to_tf32(va.w));
        *(uint4*)&As[row * AS_STRIDE + c4 * 4] = ta;
        float4 vb = *(const float4*)(xb + (size_t)(j0 + row) * C + c4 * 4);
        uint4 tb = make_uint4(to_tf32(vb.x), to_tf32(vb.y), to_tf32(vb.z), to_tf32(vb.w));
        *(uint4*)&Bs[row * AS_STRIDE + c4 * 4] = tb;
    }
    __syncthreads();

    {
        int r = tid & 127;
        const uint32_t* Row = ((tid < 128) ? As : Bs) + r * AS_STRIDE;
        float s = 0.0f;
        #pragma unroll
        for (int k = 0; k < 128; k += 4) {
            float4 v = *(const float4*)&Row[k];
            s = fmaf(v.x, v.x, s); s = fmaf(v.y, v.y, s);
            s = fmaf(v.z, v.z, s); s = fmaf(v.w, v.w, s);
        }
        sxx[tid] = s;
    }

    int warp_m = (wid >> 2) * 64;
    int warp_n = (wid & 3) * 32;

    float acc[4][4][4];
    #pragma unroll
    for (int e = 0; e < 4; ++e)
        #pragma unroll
        for (int f = 0; f < 4; ++f)
            #pragma unroll
            for (int q = 0; q < 4; ++q) acc[e][f][q] = 0.0f;

    int abase = (warp_m + grp) * AS_STRIDE + tg;
    int bbase = (warp_n + grp) * AS_STRIDE + tg;

    #pragma unroll 2
    for (int kb = 0; kb < 128; kb += 8) {
        uint32_t a[4][4], bf[4][2];
        #pragma unroll
        for (int e = 0; e < 4; ++e) {
            int r = abase + 16 * e * AS_STRIDE + kb;
            a[e][0] = As[r];
            a[e][1] = As[r + 8 * AS_STRIDE];
            a[e][2] = As[r + 4];
            a[e][3] = As[r + 8 * AS_STRIDE + 4];
        }
        #pragma unroll
        for (int f = 0; f < 4; ++f) {
            int r = bbase + 8 * f * AS_STRIDE + kb;
            bf[f][0] = Bs[r];
            bf[f][1] = Bs[r + 4];
        }
        #pragma unroll
        for (int e = 0; e < 4; ++e)
            #pragma unroll
            for (int f = 0; f < 4; ++f)
                mma_tf32(acc[e][f], a[e], bf[f]);
    }

    __syncthreads();

    float xi[4][2], xj[4][2];
    #pragma unroll
    for (int e = 0; e < 4; ++e) {
        int il = warp_m + 16 * e + grp;
        xi[e][0] = sxx[il];
        xi[e][1] = sxx[il + 8];
    }
    #pragma unroll
    for (int f = 0; f < 4; ++f) {
        int jl = warp_n + 8 * f + 2 * tg;
        xj[f][0] = sxx[128 + jl];
        xj[f][1] = sxx[128 + jl + 1];
    }

    __half* S = (__half*)sm;

    #pragma unroll
    for (int e = 0; e < 4; ++e) {
        int il = warp_m + 16 * e + grp;
        #pragma unroll
        for (int f = 0; f < 4; ++f) {
            int jl = warp_n + 8 * f + 2 * tg;
            float d00 = fmaf(-2.0f, acc[e][f][0], xi[e][0] + xj[f][0]);
            float d01 = fmaf(-2.0f, acc[e][f][1], xi[e][0] + xj[f][1]);
            float d10 = fmaf(-2.0f, acc[e][f][2], xi[e][1] + xj[f][0]);
            float d11 = fmaf(-2.0f, acc[e][f][3], xi[e][1] + xj[f][1]);
            float s00 = fsqrt_approx(fmaxf(d00, 0.0f));
            float s01 = fsqrt_approx(fmaxf(d01, 0.0f));
            float s10 = fsqrt_approx(fmaxf(d10, 0.0f));
            float s11 = fsqrt_approx(fmaxf(d11, 0.0f));
            *(__half2*)&S[il * HS_STRIDE + jl]       = __floats2half2_rn(s00, s01);
            *(__half2*)&S[(il + 8) * HS_STRIDE + jl] = __floats2half2_rn(s10, s11);
        }
    }
    __syncthreads();

    {
        long bbase2 = (long)b * LUP;
        #pragma unroll
        for (int q = tid; q < 128 * 128; q += 256) {
            int m = q >> 7, jj = q & 127;
            int i2 = i0 + m, j2 = j0 + jj;
            if (j2 > i2) {
                long ro = (long)i2 * (2 * T - 1 - i2) / 2 - i2 - 1;
                g_up[bbase2 + ro + j2] = S[m * HS_STRIDE + jj];
            }
        }
    }
}

// ---------------------------------------------------------------------------
// Kernel 2 (v6.3): HMMA conv, multi-chunk blocks.
// Grid 31 x NB; each block stages weights + builds MMA fragments ONCE, then
// loops over 11 consecutive 1536-input chunks (341 = 31*11), running the
// L0..L7 pipeline per chunk. Pipeline body identical to the 94.6us build.
// ---------------------------------------------------------------------------
__global__ __launch_bounds__(256) void conv_kernel(
    const float* __restrict__ w0, const float* __restrict__ b0,
    const float* __restrict__ w1, const float* __restrict__ b1,
    const float* __restrict__ w2, const float* __restrict__ b2,
    const float* __restrict__ w3, const float* __restrict__ b3,
    const float* __restrict__ w4, const float* __restrict__ b4,
    const float* __restrict__ w5, const float* __restrict__ b5,
    const float* __restrict__ w6, const float* __restrict__ b6,
    const float* __restrict__ w7, const float* __restrict__ b7,
    float* __restrict__ out)
{
    __shared__ float  wgt[860];
    __shared__ __align__(16) __half H0[6144];    // L0 out: 768 pos x 8ch
    __shared__ __align__(16) __half H1[3072];    // L1 out: 384 pos
    __shared__ __align__(16) __half H2[1536];    // L2 out: 192 pos
    __shared__ float  F3[768];     // L3 out: 96 pos (f32)
    __shared__ float  F4[384];     // L4 out: 48 pos
    __shared__ float  F5[192];     // L5 out: 24 pos
    __shared__ float  F6[96];      // L6 out: 12 pos

    int tid = threadIdx.x;
    int wid = tid >> 5;
    int lane = tid & 31;
    int c   = tid & 7;
    int b   = blockIdx.y;

    // ---- stage weights (once per block) ----
    if (tid < 128) {
        wgt[ 24 + tid] = w1[tid];
        wgt[152 + tid] = w2[tid];
        wgt[280 + tid] = w3[tid];
        wgt[408 + tid] = w4[tid];
        wgt[536 + tid] = w5[tid];
        wgt[664 + tid] = w6[tid];
    } else {
        int u = tid - 128;
        if (u < 16)       wgt[u]            = w0[u];
        else if (u < 24)  wgt[u]            = b0[u - 16];
        else if (u < 32)  wgt[792 + (u-24)] = b1[u-24];
        else if (u < 40)  wgt[800 + (u-32)] = b2[u-32];
        else if (u < 48)  wgt[808 + (u-40)] = b3[u-40];
        else if (u < 56)  wgt[816 + (u-48)] = b4[u-48];
        else if (u < 64)  wgt[824 + (u-56)] = b5[u-56];
        else if (u < 72)  wgt[832 + (u-64)] = b6[u-64];
        else if (u < 88)  wgt[840 + (u-72)] = w7[u-72];
        else if (u == 88) wgt[856]          = b7[0];
    }
    __syncthreads();

    // ---- build register B-fragments + biases (once per block) ----
    int g = lane >> 2, tq = lane & 3;
    uint32_t bf1[2], bf2[2], bf3[2];
    float bi1x, bi1y, bi2x, bi2y, bi3x, bi3y;
    {
        const float* W;
        W = wgt + 24;
        bf1[0] = pack_h2(W[g*16 + 4*tq],     W[g*16 + 4*tq + 2]);
        bf1[1] = pack_h2(W[g*16 + 4*tq + 1], W[g*16 + 4*tq + 3]);
        bi1x = wgt[792 + 2*tq]; bi1y = wgt[792 + 2*tq + 1];
        W = wgt + 152;
        bf2[0] = pack_h2(W[g*16 + 4*tq],     W[g*16 + 4*tq + 2]);
        bf2[1] = pack_h2(W[g*16 + 4*tq + 1], W[g*16 + 4*tq + 3]);
        bi2x = wgt[800 + 2*tq]; bi2y = wgt[800 + 2*tq + 1];
        W = wgt + 280;
        bf3[0] = pack_h2(W[g*16 + 4*tq],     W[g*16 + 4*tq + 2]);
        bf3[1] = pack_h2(W[g*16 + 4*tq + 1], W[g*16 + 4*tq + 3]);
        bi3x = wgt[808 + 2*tq]; bi3y = wgt[808 + 2*tq + 1];
    }

    // L0 register weights (once per block)
    float w0r[16], b0r[8];
    #pragma unroll
    for (int k = 0; k < 16; ++k) w0r[k] = wgt[k];
    #pragma unroll
    for (int k = 0; k < 8; ++k)  b0r[k] = wgt[16 + k];

    // ---- chunk loop: 11 chunks of 1536 inputs / 6 outputs each ----
    #pragma unroll 1
    for (int ci = 0; ci < 11; ++ci) {
        int blk = blockIdx.x * 11 + ci;     // 0..340

        // ---- L0: one thread per position, LDG direct from g_up ----
        {
            const __half2* gin = (const __half2*)(g_up + (size_t)b * LUP + (size_t)blk * 1536);
            #pragma unroll
            for (int it = 0; it < 3; ++it) {
                int p = it * 256 + tid;              // 0..767
                float2 u = __half22float2(gin[p]);
                float o[8];
                #pragma unroll
                for (int cc = 0; cc < 8; ++cc)
                    o[cc] = lrelu(fmaf(w0r[2*cc], u.x, fmaf(w0r[2*cc + 1], u.y, b0r[cc])));
                uint4 pk = make_uint4(pack_h2(o[0], o[1]), pack_h2(o[2], o[3]),
                                      pack_h2(o[4], o[5]), pack_h2(o[6], o[7]));
                *(uint4*)((char*)H0 + p * 16) = pk;
            }
        }
        __syncthreads();

        // ---- L1: H0 (768 pos) -> H1 (384 pos), 24 chunks of 16 ----
        #pragma unroll 1
        for (int ch = wid; ch < 24; ch += 8) {
            const char* base = (const char*)H0 + (ch * 16 + g) * 32 + tq * 4;
            uint32_t a[4];
            a[0] = *(const uint32_t*)(base);
            a[1] = *(const uint32_t*)(base + 256);
            a[2] = *(const uint32_t*)(base + 16);
            a[3] = *(const uint32_t*)(base + 272);
            float d[4] = {bi1x, bi1y, bi1x, bi1y};
            mma_f16(d, a, bf1);
            uint32_t h01 = pack_h2(lrelu(d[0]), lrelu(d[1]));
            uint32_t h23 = pack_h2(lrelu(d[2]), lrelu(d[3]));
            char* ob = (char*)H1 + (ch * 16 + g) * 16 + tq * 4;
            *(uint32_t*)ob = h01;
            *(uint32_t*)(ob + 128) = h23;
        }
        __syncthreads();

        // ---- L2: H1 (384 pos) -> H2 (192 pos), 12 chunks ----
        #pragma unroll 1
        for (int ch = wid; ch < 12; ch += 8) {
            const char* base = (const char*)H1 + (ch * 16 + g) * 32 + tq * 4;
            uint32_t a[4];
            a[0] = *(const uint32_t*)(base);
            a[1] = *(const uint32_t*)(base + 256);
            a[2] = *(const uint32_t*)(base + 16);
            a[3] = *(const uint32_t*)(base + 272);
            float d[4] = {bi2x, bi2y, bi2x, bi2y};
            mma_f16(d, a, bf2);
            uint32_t h01 = pack_h2(lrelu(d[0]), lrelu(d[1]));
            uint32_t h23 = pack_h2(lrelu(d[2]), lrelu(d[3]));
            char* ob = (char*)H2 + (ch * 16 + g) * 16 + tq * 4;
            *(uint32_t*)ob = h01;
            *(uint32_t*)(ob + 128) = h23;
        }
        __syncthreads();

        // ---- L3: H2 (192 pos) -> F3 (96 pos, f32 out), 6 chunks ----
        if (wid < 6) {
            int ch = wid;
            const char* base = (const char*)H2 + (ch * 16 + g) * 32 + tq * 4;
            uint32_t a[4];
            a[0] = *(const uint32_t*)(base);
            a[1] = *(const uint32_t*)(base + 256);
            a[2] = *(const uint32_t*)(base + 16);
            a[3] = *(const uint32_t*)(base + 272);
            float d[4] = {bi3x, bi3y, bi3x, bi3y};
            mma_f16(d, a, bf3);
            float* ob = F3 + (ch * 16 + g) * 8 + 2 * tq;
            ob[0]  = lrelu(d[0]);  ob[1]      = lrelu(d[1]);
            ob[64] = lrelu(d[2]);  ob[64 + 1] = lrelu(d[3]);
        }
        __syncthreads();

        // ---- tail f32 scalar layers ----
        // L4: 384 outputs, strided
        for (int q = tid; q < 384; q += 256) {
            int p = q >> 3;
            int cc = q & 7;
            const float4* s4 = (const float4*)(F3 + 16 * p);
            const float4* Wc = (const float4*)(wgt + 408 + cc * 16);
            float4 wrA = Wc[0], wrB = Wc[1], wrC = Wc[2], wrD = Wc[3];
            float4 a0 = s4[0], a1 = s4[1], a2 = s4[2], a3 = s4[3];
            float acc = wgt[816 + cc];
            acc = fmaf(wrA.x, a0.x, acc); acc = fmaf(wrA.y, a2.x, acc);
            acc = fmaf(wrA.z, a0.y, acc); acc = fmaf(wrA.w, a2.y, acc);
            acc = fmaf(wrB.x, a0.z, acc); acc = fmaf(wrB.y, a2.z, acc);
            acc = fmaf(wrB.z, a0.w, acc); acc = fmaf(wrB.w, a2.w, acc);
            acc = fmaf(wrC.x, a1.x, acc); acc = fmaf(wrC.y, a3.x, acc);
            acc = fmaf(wrC.z, a1.y, acc); acc = fmaf(wrC.w, a3.y, acc);
            acc = fmaf(wrD.x, a1.z, acc); acc = fmaf(wrD.y, a3.z, acc);
            acc = fmaf(wrD.z, a1.w, acc); acc = fmaf(wrD.w, a3.w, acc);
            F4[p * 8 + cc] = lrelu(acc);
        }
        __syncthreads();
        // L5: 192 outputs
        if (tid < 192) {
            int p = tid >> 3;
            const float4* s4 = (const float4*)(F4 + 16 * p);
            const float4* Wc = (const float4*)(wgt + 536 + c * 16);
            float4 wrA = Wc[0], wrB = Wc[1], wrC = Wc[2], wrD = Wc[3];
            float4 a0 = s4[0], a1 = s4[1], a2 = s4[2], a3 = s4[3];
            float acc = wgt[824 + c];
            acc = fmaf(wrA.x, a0.x, acc); acc = fmaf(wrA.y, a2.x, acc);
            acc = fmaf(wrA.z, a0.y, acc); acc = fmaf(wrA.w, a2.y, acc);
            acc = fmaf(wrB.x, a0.z, acc); acc = fmaf(wrB.y, a2.z, acc);
            acc = fmaf(wrB.z, a0.w, acc); acc = fmaf(wrB.w, a2.w, acc);
            acc = fmaf(wrC.x, a1.x, acc); acc = fmaf(wrC.y, a3.x, acc);
            acc = fmaf(wrC.z, a1.y, acc); acc = fmaf(wrC.w, a3.y, acc);
            acc = fmaf(wrD.x, a1.z, acc); acc = fmaf(wrD.y, a3.z, acc);
            acc = fmaf(wrD.z, a1.w, acc); acc = fmaf(wrD.w, a3.w, acc);
            F5[p * 8 + c] = lrelu(acc);
        }
        __syncthreads();
        // L6: 96 outputs
        if (tid < 96) {
            int p = tid >> 3;
            const float4* s4 = (const float4*)(F5 + 16 * p);
            const float4* Wc = (const float4*)(wgt + 664 + c * 16);
            float4 wrA = Wc[0], wrB = Wc[1], wrC = Wc[2], wrD = Wc[3];
            float4 a0 = s4[0], a1 = s4[1], a2 = s4[2], a3 = s4[3];
            float acc = wgt[832 + c];
            acc = fmaf(wrA.x, a0.x, acc); acc = fmaf(wrA.y, a2.x, acc);
            acc = fmaf(wrA.z, a0.y, acc); acc = fmaf(wrA.w, a2.y, acc);
            acc = fmaf(wrB.x, a0.z, acc); acc = fmaf(wrB.y, a2.z, acc);
            acc = fmaf(wrB.z, a0.w, acc); acc = fmaf(wrB.w, a2.w, acc);
            acc = fmaf(wrC.x, a1.x, acc); acc = fmaf(wrC.y, a3.x, acc);
            acc = fmaf(wrC.z, a1.y, acc); acc = fmaf(wrC.w, a3.y, acc);
            acc = fmaf(wrD.x, a1.z, acc); acc = fmaf(wrD.y, a3.z, acc);
            acc = fmaf(wrD.z, a1.w, acc); acc = fmaf(wrD.w, a3.w, acc);
            F6[p * 8 + c] = lrelu(acc);
        }
        __syncthreads();
        // L7: 6 outputs, no activation
        if (tid < 6) {
            const float* s0 = F6 + 16 * tid;
            const float4* Wc = (const float4*)(wgt + 840);
            float4 wa = Wc[0], wb = Wc[1], wc2 = Wc[2], wd = Wc[3];
            float acc = wgt[856];
            acc = fmaf(wa.x,  s0[0], acc); acc = fmaf(wa.y,  s0[8],  acc);
            acc = fmaf(wa.z,  s0[1], acc); acc = fmaf(wa.w,  s0[9],  acc);
            acc = fmaf(wb.x,  s0[2], acc); acc = fmaf(wb.y,  s0[10], acc);
            acc = fmaf(wb.z,  s0[3], acc); acc = fmaf(wb.w,  s0[11], acc);
            acc = fmaf(wc2.x, s0[4], acc); acc = fmaf(wc2.y, s0[12], acc);
            acc = fmaf(wc2.z, s0[5], acc); acc = fmaf(wc2.w, s0[13], acc);
            acc = fmaf(wd.x,  s0[6], acc); acc = fmaf(wd.y,  s0[14], acc);
            acc = fmaf(wd.z,  s0[7], acc); acc = fmaf(wd.w,  s0[15], acc);
            out[b * NOUT + blk * 6 + tid] = acc;
        }
        __syncthreads();   // F6 safe before next iteration's L6 writes
    }
}

// ---------------------------------------------------------------------------
extern "C" void kernel_launch(void* const* d_in, const int* in_sizes, int n_in,
                              void* d_out, int out_size) {
    const float* x = (const float*)d_in[0];
    const float* w[8];
    const float* bb[8];
    for (int i = 0; i < 8; ++i) {
        w[i]  = (const float*)d_in[1 + 2 * i];
        bb[i] = (const float*)d_in[2 + 2 * i];
    }
    float* out = (float*)d_out;

    cudaFuncSetAttribute(dist_kernel,
                         cudaFuncAttributeMaxDynamicSharedMemorySize, DIST_SMEM);

    dist_kernel<<<dim3(36, NB), 256, DIST_SMEM>>>(x);
    conv_kernel<<<dim3(31, NB), 256>>>(
        w[0], bb[0], w[1], bb[1], w[2], bb[2], w[3], bb[3],
        w[4], bb[4], w[5], bb[5], w[6], bb[6], w[7], bb[7], out);
}

// round 15
// speedup vs baseline: 1.1650x; 1.1650x over previous
#include <cuda_runtime.h>
#include <cuda_fp16.h>
#include <math.h>
#include <stdint.h>

#define T 1024
#define C 128
#define NB 16
#define LUP 523776          // T*(T-1)/2
#define NOUT 2046           // LUP / 256
#define LEAK 0.2f

// ---------------------------------------------------------------------------
// Device globals (scratch)
// ---------------------------------------------------------------------------
__device__ __half g_up[(size_t)NB * LUP];  // packed upper-triangle distances (fp16)

// ---------------------------------------------------------------------------
// Helpers
// ---------------------------------------------------------------------------
__device__ __forceinline__ uint32_t to_tf32(float f) {
    uint32_t r;
    asm("cvt.rna.tf32.f32 %0, %1;" : "=r"(r) : "f"(f));
    return r;
}

__device__ __forceinline__ void mma_tf32(float* d, const uint32_t* a, const uint32_t* b) {
    asm volatile(
        "mma.sync.aligned.m16n8k8.row.col.f32.tf32.tf32.f32 "
        "{%0,%1,%2,%3}, {%4,%5,%6,%7}, {%8,%9}, {%0,%1,%2,%3};"
        : "+f"(d[0]), "+f"(d[1]), "+f"(d[2]), "+f"(d[3])
        : "r"(a[0]), "r"(a[1]), "r"(a[2]), "r"(a[3]),
          "r"(b[0]), "r"(b[1]));
}

__device__ __forceinline__ void mma_f16(float* d, const uint32_t* a, const uint32_t* b) {
    asm volatile(
        "mma.sync.aligned.m16n8k16.row.col.f32.f16.f16.f32 "
        "{%0,%1,%2,%3}, {%4,%5,%6,%7}, {%8,%9}, {%0,%1,%2,%3};"
        : "+f"(d[0]), "+f"(d[1]), "+f"(d[2]), "+f"(d[3])
        : "r"(a[0]), "r"(a[1]), "r"(a[2]), "r"(a[3]),
          "r"(b[0]), "r"(b[1]));
}

__device__ __forceinline__ float lrelu(float v) {
    return fmaxf(v, LEAK * v);
}

__device__ __forceinline__ float fsqrt_approx(float v) {
    float r;
    asm("sqrt.approx.f32 %0, %1;" : "=f"(r) : "f"(v));
    return r;
}

__device__ __forceinline__ uint32_t pack_h2(float x, float y) {
    __half2 h = __floats2half2_rn(x, y);
    return *(uint32_t*)&h;
}

// ---------------------------------------------------------------------------
// Kernel 1: tf32 mma.sync Gram tiles -> packed fp16 sqrt distances.
// sxx fused into the load loop: each warp load-iteration covers one full
// 128-elem row, so the row norm is a warp-reduction of the tf32 values
// already in registers (replaces the separate 4k-LDS.128 sxx pass).
// ---------------------------------------------------------------------------
#define AS_STRIDE 132
#define AS_BYTES  (128 * AS_STRIDE * 4)       // 67584
#define DIST_SMEM (2 * AS_BYTES + 1024)       // + sxx[256]
#define HS_STRIDE 130

__global__ __launch_bounds__(256) void dist_kernel(const float* __restrict__ x) {
    extern __shared__ __align__(16) unsigned char sm[];
    uint32_t* As = (uint32_t*)sm;
    uint32_t* Bs = (uint32_t*)(sm + AS_BYTES);
    float* sxx   = (float*)(sm + 2 * AS_BYTES);

    int tid = threadIdx.x;
    int wid = tid >> 5;
    int lane = tid & 31;
    int grp = lane >> 2;
    int tg  = lane & 3;

    int b = blockIdx.y;
    int t = blockIdx.x;
    int ti = 0, rem = t;
    while (rem >= 8 - ti) { rem -= 8 - ti; ++ti; }
    int tj = ti + rem;
    int i0 = ti * 128, j0 = tj * 128;

    const float* xb = x + (size_t)b * T * C;

    #pragma unroll
    for (int it = 0; it < 16; ++it) {
        int f4 = it * 256 + tid;
        int row = f4 >> 5, c4 = f4 & 31;       // row is warp-uniform
        float4 va = *(const float4*)(xb + (size_t)(i0 + row) * C + c4 * 4);
        uint4 ta = make_uint4(to_tf32(va.x), to_tf32(va.y), to_tf32(va.z), to_tf32(va.w));
        *(uint4*)&As[row * AS_STRIDE + c4 * 4] = ta;
        float4 vb = *(const float4*)(xb + (size_t)(j0 + row) * C + c4 * 4);
        uint4 tb = make_uint4(to_tf32(vb.x), to_tf32(vb.y), to_tf32(vb.z), to_tf32(vb.w));
        *(uint4*)&Bs[row * AS_STRIDE + c4 * 4] = tb;

        // fused row-norms from the tf32 values (bit-identical to old pass)
        float ax = __uint_as_float(ta.x), ay = __uint_as_float(ta.y);
        float az = __uint_as_float(ta.z), aw = __uint_as_float(ta.w);
        float bx = __uint_as_float(tb.x), by = __uint_as_float(tb.y);
        float bz = __uint_as_float(tb.z), bw = __uint_as_float(tb.w);
        float sa = fmaf(ax, ax, fmaf(ay, ay, fmaf(az, az, aw * aw)));
        float sb = fmaf(bx, bx, fmaf(by, by, fmaf(bz, bz, bw * bw)));
        #pragma unroll
        for (int o = 16; o; o >>= 1) {
            sa += __shfl_xor_sync(0xffffffffu, sa, o);
            sb += __shfl_xor_sync(0xffffffffu, sb, o);
        }
        if (lane == 0) {
            sxx[row] = sa;
            sxx[128 + row] = sb;
        }
    }
    __syncthreads();

    int warp_m = (wid >> 2) * 64;
    int warp_n = (wid & 3) * 32;

    float acc[4][4][4];
    #pragma unroll
    for (int e = 0; e < 4; ++e)
        #pragma unroll
        for (int f = 0; f < 4; ++f)
            #pragma unroll
            for (int q = 0; q < 4; ++q) acc[e][f][q] = 0.0f;

    int abase = (warp_m + grp) * AS_STRIDE + tg;
    int bbase = (warp_n + grp) * AS_STRIDE + tg;

    #pragma unroll 2
    for (int kb = 0; kb < 128; kb += 8) {
        uint32_t a[4][4], bf[4][2];
        #pragma unroll
        for (int e = 0; e < 4; ++e) {
            int r = abase + 16 * e * AS_STRIDE + kb;
            a[e][0] = As[r];
            a[e][1] = As[r + 8 * AS_STRIDE];
            a[e][2] = As[r + 4];
            a[e][3] = As[r + 8 * AS_STRIDE + 4];
        }
        #pragma unroll
        for (int f = 0; f < 4; ++f) {
            int r = bbase + 8 * f * AS_STRIDE + kb;
            bf[f][0] = Bs[r];
            bf[f][1] = Bs[r + 4];
        }
        #pragma unroll
        for (int e = 0; e < 4; ++e)
            #pragma unroll
            for (int f = 0; f < 4; ++f)
                mma_tf32(acc[e][f], a[e], bf[f]);
    }

    // barrier: orders sxx writes before reads, As/Bs reads before staging reuse
    __syncthreads();

    float xi[4][2], xj[4][2];
    #pragma unroll
    for (int e = 0; e < 4; ++e) {
        int il = warp_m + 16 * e + grp;
        xi[e][0] = sxx[il];
        xi[e][1] = sxx[il + 8];
    }
    #pragma unroll
    for (int f = 0; f < 4; ++f) {
        int jl = warp_n + 8 * f + 2 * tg;
        xj[f][0] = sxx[128 + jl];
        xj[f][1] = sxx[128 + jl + 1];
    }

    __half* S = (__half*)sm;

    #pragma unroll
    for (int e = 0; e < 4; ++e) {
        int il = warp_m + 16 * e + grp;
        #pragma unroll
        for (int f = 0; f < 4; ++f) {
            int jl = warp_n + 8 * f + 2 * tg;
            float d00 = fmaf(-2.0f, acc[e][f][0], xi[e][0] + xj[f][0]);
            float d01 = fmaf(-2.0f, acc[e][f][1], xi[e][0] + xj[f][1]);
            float d10 = fmaf(-2.0f, acc[e][f][2], xi[e][1] + xj[f][0]);
            float d11 = fmaf(-2.0f, acc[e][f][3], xi[e][1] + xj[f][1]);
            float s00 = fsqrt_approx(fmaxf(d00, 0.0f));
            float s01 = fsqrt_approx(fmaxf(d01, 0.0f));
            float s10 = fsqrt_approx(fmaxf(d10, 0.0f));
            float s11 = fsqrt_approx(fmaxf(d11, 0.0f));
            *(__half2*)&S[il * HS_STRIDE + jl]       = __floats2half2_rn(s00, s01);
            *(__half2*)&S[(il + 8) * HS_STRIDE + jl] = __floats2half2_rn(s10, s11);
        }
    }
    __syncthreads();

    {
        long bbase2 = (long)b * LUP;
        #pragma unroll
        for (int q = tid; q < 128 * 128; q += 256) {
            int m = q >> 7, jj = q & 127;
            int i2 = i0 + m, j2 = j0 + jj;
            if (j2 > i2) {
                long ro = (long)i2 * (2 * T - 1 - i2) / 2 - i2 - 1;
                g_up[bbase2 + ro + j2] = S[m * HS_STRIDE + jj];
            }
        }
    }
}

// ---------------------------------------------------------------------------
// Kernel 2 (v6.2): HMMA conv — verbatim from the 94.6us round-13 build
// (grid 341 x NB, one chunk per block).
// ---------------------------------------------------------------------------
__global__ __launch_bounds__(256) void conv_kernel(
    const float* __restrict__ w0, const float* __restrict__ b0,
    const float* __restrict__ w1, const float* __restrict__ b1,
    const float* __restrict__ w2, const float* __restrict__ b2,
    const float* __restrict__ w3, const float* __restrict__ b3,
    const float* __restrict__ w4, const float* __restrict__ b4,
    const float* __restrict__ w5, const float* __restrict__ b5,
    const float* __restrict__ w6, const float* __restrict__ b6,
    const float* __restrict__ w7, const float* __restrict__ b7,
    float* __restrict__ out)
{
    __shared__ float  wgt[860];
    __shared__ __align__(16) __half H0[6144];    // L0 out: 768 pos x 8ch
    __shared__ __align__(16) __half H1[3072];    // L1 out: 384 pos
    __shared__ __align__(16) __half H2[1536];    // L2 out: 192 pos
    __shared__ float  F3[768];     // L3 out: 96 pos (f32)
    __shared__ float  F4[384];     // L4 out: 48 pos
    __shared__ float  F5[192];     // L5 out: 24 pos
    __shared__ float  F6[96];      // L6 out: 12 pos

    int tid = threadIdx.x;
    int wid = tid >> 5;
    int lane = tid & 31;
    int c   = tid & 7;
    int b   = blockIdx.y;
    int blk = blockIdx.x;        // 0..340

    // ---- stage weights ----
    if (tid < 128) {
        wgt[ 24 + tid] = w1[tid];
        wgt[152 + tid] = w2[tid];
        wgt[280 + tid] = w3[tid];
        wgt[408 + tid] = w4[tid];
        wgt[536 + tid] = w5[tid];
        wgt[664 + tid] = w6[tid];
    } else {
        int u = tid - 128;
        if (u < 16)       wgt[u]            = w0[u];
        else if (u < 24)  wgt[u]            = b0[u - 16];
        else if (u < 32)  wgt[792 + (u-24)] = b1[u-24];
        else if (u < 40)  wgt[800 + (u-32)] = b2[u-32];
        else if (u < 48)  wgt[808 + (u-40)] = b3[u-40];
        else if (u < 56)  wgt[816 + (u-48)] = b4[u-48];
        else if (u < 64)  wgt[824 + (u-56)] = b5[u-56];
        else if (u < 72)  wgt[832 + (u-64)] = b6[u-64];
        else if (u < 88)  wgt[840 + (u-72)] = w7[u-72];
        else if (u == 88) wgt[856]          = b7[0];
    }
    __syncthreads();

    // ---- build register B-fragments + biases for layers 1..3 ----
    int g = lane >> 2, tq = lane & 3;
    uint32_t bf1[2], bf2[2], bf3[2];
    float bi1x, bi1y, bi2x, bi2y, bi3x, bi3y;
    {
        const float* W;
        W = wgt + 24;
        bf1[0] = pack_h2(W[g*16 + 4*tq],     W[g*16 + 4*tq + 2]);
        bf1[1] = pack_h2(W[g*16 + 4*tq + 1], W[g*16 + 4*tq + 3]);
        bi1x = wgt[792 + 2*tq]; bi1y = wgt[792 + 2*tq + 1];
        W = wgt + 152;
        bf2[0] = pack_h2(W[g*16 + 4*tq],     W[g*16 + 4*tq + 2]);
        bf2[1] = pack_h2(W[g*16 + 4*tq + 1], W[g*16 + 4*tq + 3]);
        bi2x = wgt[800 + 2*tq]; bi2y = wgt[800 + 2*tq + 1];
        W = wgt + 280;
        bf3[0] = pack_h2(W[g*16 + 4*tq],     W[g*16 + 4*tq + 2]);
        bf3[1] = pack_h2(W[g*16 + 4*tq + 1], W[g*16 + 4*tq + 3]);
        bi3x = wgt[808 + 2*tq]; bi3y = wgt[808 + 2*tq + 1];
    }

    // ---- L0: one thread per position, LDG direct from g_up, STS.128 out ----
    {
        float w0r[16], b0r[8];
        #pragma unroll
        for (int k = 0; k < 16; ++k) w0r[k] = wgt[k];
        #pragma unroll
        for (int k = 0; k < 8; ++k)  b0r[k] = wgt[16 + k];

        const __half2* gin = (const __half2*)(g_up + (size_t)b * LUP + (size_t)blk * 1536);
        #pragma unroll
        for (int it = 0; it < 3; ++it) {
            int p = it * 256 + tid;              // 0..767
            float2 u = __half22float2(gin[p]);
            float o[8];
            #pragma unroll
            for (int cc = 0; cc < 8; ++cc)
                o[cc] = lrelu(fmaf(w0r[2*cc], u.x, fmaf(w0r[2*cc + 1], u.y, b0r[cc])));
            uint4 pk = make_uint4(pack_h2(o[0], o[1]), pack_h2(o[2], o[3]),
                                  pack_h2(o[4], o[5]), pack_h2(o[6], o[7]));
            *(uint4*)((char*)H0 + p * 16) = pk;
        }
    }
    __syncthreads();

    // ---- L1: H0 (768 pos) -> H1 (384 pos), 24 chunks of 16 ----
    #pragma unroll 1
    for (int ch = wid; ch < 24; ch += 8) {
        const char* base = (const char*)H0 + (ch * 16 + g) * 32 + tq * 4;
        uint32_t a[4];
        a[0] = *(const uint32_t*)(base);
        a[1] = *(const uint32_t*)(base + 256);
        a[2] = *(const uint32_t*)(base + 16);
        a[3] = *(const uint32_t*)(base + 272);
        float d[4] = {bi1x, bi1y, bi1x, bi1y};
        mma_f16(d, a, bf1);
        uint32_t h01 = pack_h2(lrelu(d[0]), lrelu(d[1]));
        uint32_t h23 = pack_h2(lrelu(d[2]), lrelu(d[3]));
        char* ob = (char*)H1 + (ch * 16 + g) * 16 + tq * 4;
        *(uint32_t*)ob = h01;
        *(uint32_t*)(ob + 128) = h23;
    }
    __syncthreads();

    // ---- L2: H1 (384 pos) -> H2 (192 pos), 12 chunks ----
    #pragma unroll 1
    for (int ch = wid; ch < 12; ch += 8) {
        const char* base = (const char*)H1 + (ch * 16 + g) * 32 + tq * 4;
        uint32_t a[4];
        a[0] = *(const uint32_t*)(base);
        a[1] = *(const uint32_t*)(base + 256);
        a[2] = *(const uint32_t*)(base + 16);
        a[3] = *(const uint32_t*)(base + 272);
        float d[4] = {bi2x, bi2y, bi2x, bi2y};
        mma_f16(d, a, bf2);
        uint32_t h01 = pack_h2(lrelu(d[0]), lrelu(d[1]));
        uint32_t h23 = pack_h2(lrelu(d[2]), lrelu(d[3]));
        char* ob = (char*)H2 + (ch * 16 + g) * 16 + tq * 4;
        *(uint32_t*)ob = h01;
        *(uint32_t*)(ob + 128) = h23;
    }
    __syncthreads();

    // ---- L3: H2 (192 pos) -> F3 (96 pos, f32 out), 6 chunks ----
    if (wid < 6) {
        int ch = wid;
        const char* base = (const char*)H2 + (ch * 16 + g) * 32 + tq * 4;
        uint32_t a[4];
        a[0] = *(const uint32_t*)(base);
        a[1] = *(const uint32_t*)(base + 256);
        a[2] = *(const uint32_t*)(base + 16);
        a[3] = *(const uint32_t*)(base + 272);
        float d[4] = {bi3x, bi3y, bi3x, bi3y};
        mma_f16(d, a, bf3);
        float* ob = F3 + (ch * 16 + g) * 8 + 2 * tq;
        ob[0]  = lrelu(d[0]);  ob[1]      = lrelu(d[1]);
        ob[64] = lrelu(d[2]);  ob[64 + 1] = lrelu(d[3]);
    }
    __syncthreads();

    // ---- tail f32 scalar layers ----
    // L4: 384 outputs, strided
    for (int q = tid; q < 384; q += 256) {
        int p = q >> 3;
        int cc = q & 7;
        const float4* s4 = (const float4*)(F3 + 16 * p);
        const float4* Wc = (const float4*)(wgt + 408 + cc * 16);
        float4 wrA = Wc[0], wrB = Wc[1], wrC = Wc[2], wrD = Wc[3];
        float4 a0 = s4[0], a1 = s4[1], a2 = s4[2], a3 = s4[3];
        float acc = wgt[816 + cc];
        acc = fmaf(wrA.x, a0.x, acc); acc = fmaf(wrA.y, a2.x, acc);
        acc = fmaf(wrA.z, a0.y, acc); acc = fmaf(wrA.w, a2.y, acc);
        acc = fmaf(wrB.x, a0.z, acc); acc = fmaf(wrB.y, a2.z, acc);
        acc = fmaf(wrB.z, a0.w, acc); acc = fmaf(wrB.w, a2.w, acc);
        acc = fmaf(wrC.x, a1.x, acc); acc = fmaf(wrC.y, a3.x, acc);
        acc = fmaf(wrC.z, a1.y, acc); acc = fmaf(wrC.w, a3.y, acc);
        acc = fmaf(wrD.x, a1.z, acc); acc = fmaf(wrD.y, a3.z, acc);
        acc = fmaf(wrD.z, a1.w, acc); acc = fmaf(wrD.w, a3.w, acc);
        F4[p * 8 + cc] = lrelu(acc);
    }
    __syncthreads();
    // L5: 192 outputs
    if (tid < 192) {
        int p = tid >> 3;
        const float4* s4 = (const float4*)(F4 + 16 * p);
        const float4* Wc = (const float4*)(wgt + 536 + c * 16);
        float4 wrA = Wc[0], wrB = Wc[1], wrC = Wc[2], wrD = Wc[3];
        float4 a0 = s4[0], a1 = s4[1], a2 = s4[2], a3 = s4[3];
        float acc = wgt[824 + c];
        acc = fmaf(wrA.x, a0.x, acc); acc = fmaf(wrA.y, a2.x, acc);
        acc = fmaf(wrA.z, a0.y, acc); acc = fmaf(wrA.w, a2.y, acc);
        acc = fmaf(wrB.x, a0.z, acc); acc = fmaf(wrB.y, a2.z, acc);
        acc = fmaf(wrB.z, a0.w, acc); acc = fmaf(wrB.w, a2.w, acc);
        acc = fmaf(wrC.x, a1.x, acc); acc = fmaf(wrC.y, a3.x, acc);
        acc = fmaf(wrC.z, a1.y, acc); acc = fmaf(wrC.w, a3.y, acc);
        acc = fmaf(wrD.x, a1.z, acc); acc = fmaf(wrD.y, a3.z, acc);
        acc = fmaf(wrD.z, a1.w, acc); acc = fmaf(wrD.w, a3.w, acc);
        F5[p * 8 + c] = lrelu(acc);
    }
    __syncthreads();
    // L6: 96 outputs
    if (tid < 96) {
        int p = tid >> 3;
        const float4* s4 = (const float4*)(F5 + 16 * p);
        const float4* Wc = (const float4*)(wgt + 664 + c * 16);
        float4 wrA = Wc[0], wrB = Wc[1], wrC = Wc[2], wrD = Wc[3];
        float4 a0 = s4[0], a1 = s4[1], a2 = s4[2], a3 = s4[3];
        float acc = wgt[832 + c];
        acc = fmaf(wrA.x, a0.x, acc); acc = fmaf(wrA.y, a2.x, acc);
        acc = fmaf(wrA.z, a0.y, acc); acc = fmaf(wrA.w, a2.y, acc);
        acc = fmaf(wrB.x, a0.z, acc); acc = fmaf(wrB.y, a2.z, acc);
        acc = fmaf(wrB.z, a0.w, acc); acc = fmaf(wrB.w, a2.w, acc);
        acc = fmaf(wrC.x, a1.x, acc); acc = fmaf(wrC.y, a3.x, acc);
        acc = fmaf(wrC.z, a1.y, acc); acc = fmaf(wrC.w, a3.y, acc);
        acc = fmaf(wrD.x, a1.z, acc); acc = fmaf(wrD.y, a3.z, acc);
        acc = fmaf(wrD.z, a1.w, acc); acc = fmaf(wrD.w, a3.w, acc);
        F6[p * 8 + c] = lrelu(acc);
    }
    __syncthreads();
    // L7: 6 outputs, no activation
    if (tid < 6) {
        const float* s0 = F6 + 16 * tid;
        const float4* Wc = (const float4*)(wgt + 840);
        float4 wa = Wc[0], wb = Wc[1], wc2 = Wc[2], wd = Wc[3];
        float acc = wgt[856];
        acc = fmaf(wa.x,  s0[0], acc); acc = fmaf(wa.y,  s0[8],  acc);
        acc = fmaf(wa.z,  s0[1], acc); acc = fmaf(wa.w,  s0[9],  acc);
        acc = fmaf(wb.x,  s0[2], acc); acc = fmaf(wb.y,  s0[10], acc);
        acc = fmaf(wb.z,  s0[3], acc); acc = fmaf(wb.w,  s0[11], acc);
        acc = fmaf(wc2.x, s0[4], acc); acc = fmaf(wc2.y, s0[12], acc);
        acc = fmaf(wc2.z, s0[5], acc); acc = fmaf(wc2.w, s0[13], acc);
        acc = fmaf(wd.x,  s0[6], acc); acc = fmaf(wd.y,  s0[14], acc);
        acc = fmaf(wd.z,  s0[7], acc); acc = fmaf(wd.w,  s0[15], acc);
        out[b * NOUT + blk * 6 + tid] = acc;
    }
}

// ---------------------------------------------------------------------------
extern "C" void kernel_launch(void* const* d_in, const int* in_sizes, int n_in,
                              void* d_out, int out_size) {
    const float* x = (const float*)d_in[0];
    const float* w[8];
    const float* bb[8];
    for (int i = 0; i < 8; ++i) {
        w[i]  = (const float*)d_in[1 + 2 * i];
        bb[i] = (const float*)d_in[2 + 2 * i];
    }
    float* out = (float*)d_out;

    cudaFuncSetAttribute(dist_kernel,
                         cudaFuncAttributeMaxDynamicSharedMemorySize, DIST_SMEM);

    dist_kernel<<<dim3(36, NB), 256, DIST_SMEM>>>(x);
    conv_kernel<<<dim3(341, NB), 256>>>(
        w[0], bb[0], w[1], bb[1], w[2], bb[2], w[3], bb[3],
        w[4], bb[4], w[5], bb[5], w[6], bb[6], w[7], bb[7], out);
}

// round 16
// speedup vs baseline: 1.1789x; 1.0119x over previous
#include <cuda_runtime.h>
#include <cuda_fp16.h>
#include <math.h>
#include <stdint.h>

#define T 1024
#define C 128
#define NB 16
#define LUP 523776          // T*(T-1)/2
#define NOUT 2046           // LUP / 256
#define LEAK 0.2f

// ---------------------------------------------------------------------------
// Device globals (scratch)
// ---------------------------------------------------------------------------
__device__ __half g_up[(size_t)NB * LUP];  // packed upper-triangle distances (fp16)

// ---------------------------------------------------------------------------
// Helpers
// ---------------------------------------------------------------------------
__device__ __forceinline__ uint32_t smem_u32(const void* p) {
    uint32_t a;
    asm("{ .reg .u64 t; cvta.to.shared.u64 t, %1; cvt.u32.u64 %0, t; }"
        : "=r"(a) : "l"(p));
    return a;
}

__device__ __forceinline__ uint32_t to_tf32(float f) {
    uint32_t r;
    asm("cvt.rna.tf32.f32 %0, %1;" : "=r"(r) : "f"(f));
    return r;
}

__device__ __forceinline__ void mma_tf32(float* d, const uint32_t* a, const uint32_t* b) {
    asm volatile(
        "mma.sync.aligned.m16n8k8.row.col.f32.tf32.tf32.f32 "
        "{%0,%1,%2,%3}, {%4,%5,%6,%7}, {%8,%9}, {%0,%1,%2,%3};"
        : "+f"(d[0]), "+f"(d[1]), "+f"(d[2]), "+f"(d[3])
        : "r"(a[0]), "r"(a[1]), "r"(a[2]), "r"(a[3]),
          "r"(b[0]), "r"(b[1]));
}

__device__ __forceinline__ void mma_f16(float* d, const uint32_t* a, const uint32_t* b) {
    asm volatile(
        "mma.sync.aligned.m16n8k16.row.col.f32.f16.f16.f32 "
        "{%0,%1,%2,%3}, {%4,%5,%6,%7}, {%8,%9}, {%0,%1,%2,%3};"
        : "+f"(d[0]), "+f"(d[1]), "+f"(d[2]), "+f"(d[3])
        : "r"(a[0]), "r"(a[1]), "r"(a[2]), "r"(a[3]),
          "r"(b[0]), "r"(b[1]));
}

// warp-collective: load the 16x16 f16 A-tile of chunk ch from a 32B/row buffer
__device__ __forceinline__ void ldsm_a(uint32_t* a, uint32_t base, int ch, int lane) {
    int mat = lane >> 3, r = lane & 7;
    uint32_t addr = base + (uint32_t)((ch * 16 + (mat & 1) * 8 + r) * 32 + (mat >> 1) * 16);
    asm volatile(
        "ldmatrix.sync.aligned.m8n8.x4.shared.b16 {%0,%1,%2,%3}, [%4];"
        : "=r"(a[0]), "=r"(a[1]), "=r"(a[2]), "=r"(a[3])
        : "r"(addr));
}

__device__ __forceinline__ float lrelu(float v) {
    return fmaxf(v, LEAK * v);
}

__device__ __forceinline__ float fsqrt_approx(float v) {
    float r;
    asm("sqrt.approx.f32 %0, %1;" : "=f"(r) : "f"(v));
    return r;
}

__device__ __forceinline__ uint32_t pack_h2(float x, float y) {
    __half2 h = __floats2half2_rn(x, y);
    return *(uint32_t*)&h;
}

// ---------------------------------------------------------------------------
// Kernel 1: tf32 mma.sync Gram tiles -> packed fp16 sqrt distances.
// (verbatim from the 94.6us round-13 build; xx as separate in-block pass)
// ---------------------------------------------------------------------------
#define AS_STRIDE 132
#define AS_BYTES  (128 * AS_STRIDE * 4)       // 67584
#define DIST_SMEM (2 * AS_BYTES + 1024)       // + sxx[256]
#define HS_STRIDE 130

__global__ __launch_bounds__(256) void dist_kernel(const float* __restrict__ x) {
    extern __shared__ __align__(16) unsigned char sm[];
    uint32_t* As = (uint32_t*)sm;
    uint32_t* Bs = (uint32_t*)(sm + AS_BYTES);
    float* sxx   = (float*)(sm + 2 * AS_BYTES);

    int tid = threadIdx.x;
    int wid = tid >> 5;
    int lane = tid & 31;
    int grp = lane >> 2;
    int tg  = lane & 3;

    int b = blockIdx.y;
    int t = blockIdx.x;
    int ti = 0, rem = t;
    while (rem >= 8 - ti) { rem -= 8 - ti; ++ti; }
    int tj = ti + rem;
    int i0 = ti * 128, j0 = tj * 128;

    const float* xb = x + (size_t)b * T * C;

    #pragma unroll
    for (int it = 0; it < 16; ++it) {
        int f4 = it * 256 + tid;
        int row = f4 >> 5, c4 = f4 & 31;
        float4 va = *(const float4*)(xb + (size_t)(i0 + row) * C + c4 * 4);
        uint4 ta = make_uint4(to_tf32(va.x), to_tf32(va.y), to_tf32(va.z), to_tf32(va.w));
        *(uint4*)&As[row * AS_STRIDE + c4 * 4] = ta;
        float4 vb = *(const float4*)(xb + (size_t)(j0 + row) * C + c4 * 4);
        uint4 tb = make_uint4(to_tf32(vb.x), to_tf32(vb.y), to_tf32(vb.z), to_tf32(vb.w));
        *(uint4*)&Bs[row * AS_STRIDE + c4 * 4] = tb;
    }
    __syncthreads();

    {
        int r = tid & 127;
        const uint32_t* Row = ((tid < 128) ? As : Bs) + r * AS_STRIDE;
        float s = 0.0f;
        #pragma unroll
        for (int k = 0; k < 128; k += 4) {
            float4 v = *(const float4*)&Row[k];
            s = fmaf(v.x, v.x, s); s = fmaf(v.y, v.y, s);
            s = fmaf(v.z, v.z, s); s = fmaf(v.w, v.w, s);
        }
        sxx[tid] = s;
    }

    int warp_m = (wid >> 2) * 64;
    int warp_n = (wid & 3) * 32;

    float acc[4][4][4];
    #pragma unroll
    for (int e = 0; e < 4; ++e)
        #pragma unroll
        for (int f = 0; f < 4; ++f)
            #pragma unroll
            for (int q = 0; q < 4; ++q) acc[e][f][q] = 0.0f;

    int abase = (warp_m + grp) * AS_STRIDE + tg;
    int bbase = (warp_n + grp) * AS_STRIDE + tg;

    #pragma unroll 2
    for (int kb = 0; kb < 128; kb += 8) {
        uint32_t a[4][4], bf[4][2];
        #pragma unroll
        for (int e = 0; e < 4; ++e) {
            int r = abase + 16 * e * AS_STRIDE + kb;
            a[e][0] = As[r];
            a[e][1] = As[r + 8 * AS_STRIDE];
            a[e][2] = As[r + 4];
            a[e][3] = As[r + 8 * AS_STRIDE + 4];
        }
        #pragma unroll
        for (int f = 0; f < 4; ++f) {
            int r = bbase + 8 * f * AS_STRIDE + kb;
            bf[f][0] = Bs[r];
            bf[f][1] = Bs[r + 4];
        }
        #pragma unroll
        for (int e = 0; e < 4; ++e)
            #pragma unroll
            for (int f = 0; f < 4; ++f)
                mma_tf32(acc[e][f], a[e], bf[f]);
    }

    __syncthreads();

    float xi[4][2], xj[4][2];
    #pragma unroll
    for (int e = 0; e < 4; ++e) {
        int il = warp_m + 16 * e + grp;
        xi[e][0] = sxx[il];
        xi[e][1] = sxx[il + 8];
    }
    #pragma unroll
    for (int f = 0; f < 4; ++f) {
        int jl = warp_n + 8 * f + 2 * tg;
        xj[f][0] = sxx[128 + jl];
        xj[f][1] = sxx[128 + jl + 1];
    }

    __half* S = (__half*)sm;

    #pragma unroll
    for (int e = 0; e < 4; ++e) {
        int il = warp_m + 16 * e + grp;
        #pragma unroll
        for (int f = 0; f < 4; ++f) {
            int jl = warp_n + 8 * f + 2 * tg;
            float d00 = fmaf(-2.0f, acc[e][f][0], xi[e][0] + xj[f][0]);
            float d01 = fmaf(-2.0f, acc[e][f][1], xi[e][0] + xj[f][1]);
            float d10 = fmaf(-2.0f, acc[e][f][2], xi[e][1] + xj[f][0]);
            float d11 = fmaf(-2.0f, acc[e][f][3], xi[e][1] + xj[f][1]);
            float s00 = fsqrt_approx(fmaxf(d00, 0.0f));
            float s01 = fsqrt_approx(fmaxf(d01, 0.0f));
            float s10 = fsqrt_approx(fmaxf(d10, 0.0f));
            float s11 = fsqrt_approx(fmaxf(d11, 0.0f));
            *(__half2*)&S[il * HS_STRIDE + jl]       = __floats2half2_rn(s00, s01);
            *(__half2*)&S[(il + 8) * HS_STRIDE + jl] = __floats2half2_rn(s10, s11);
        }
    }
    __syncthreads();

    {
        long bbase2 = (long)b * LUP;
        #pragma unroll
        for (int q = tid; q < 128 * 128; q += 256) {
            int m = q >> 7, jj = q & 127;
            int i2 = i0 + m, j2 = j0 + jj;
            if (j2 > i2) {
                long ro = (long)i2 * (2 * T - 1 - i2) / 2 - i2 - 1;
                g_up[bbase2 + ro + j2] = S[m * HS_STRIDE + jj];
            }
        }
    }
}

// ---------------------------------------------------------------------------
// Kernel 2 (v6.4): HMMA conv with ldmatrix A-fragment loads in L1/L2/L3.
// Otherwise verbatim from the 94.6us round-13 build.
// ---------------------------------------------------------------------------
__global__ __launch_bounds__(256) void conv_kernel(
    const float* __restrict__ w0, const float* __restrict__ b0,
    const float* __restrict__ w1, const float* __restrict__ b1,
    const float* __restrict__ w2, const float* __restrict__ b2,
    const float* __restrict__ w3, const float* __restrict__ b3,
    const float* __restrict__ w4, const float* __restrict__ b4,
    const float* __restrict__ w5, const float* __restrict__ b5,
    const float* __restrict__ w6, const float* __restrict__ b6,
    const float* __restrict__ w7, const float* __restrict__ b7,
    float* __restrict__ out)
{
    __shared__ float  wgt[860];
    __shared__ __align__(16) __half H0[6144];    // L0 out: 768 pos x 8ch
    __shared__ __align__(16) __half H1[3072];    // L1 out: 384 pos
    __shared__ __align__(16) __half H2[1536];    // L2 out: 192 pos
    __shared__ float  F3[768];     // L3 out: 96 pos (f32)
    __shared__ float  F4[384];     // L4 out: 48 pos
    __shared__ float  F5[192];     // L5 out: 24 pos
    __shared__ float  F6[96];      // L6 out: 12 pos

    int tid = threadIdx.x;
    int wid = tid >> 5;
    int lane = tid & 31;
    int c   = tid & 7;
    int b   = blockIdx.y;
    int blk = blockIdx.x;        // 0..340

    // ---- stage weights ----
    if (tid < 128) {
        wgt[ 24 + tid] = w1[tid];
        wgt[152 + tid] = w2[tid];
        wgt[280 + tid] = w3[tid];
        wgt[408 + tid] = w4[tid];
        wgt[536 + tid] = w5[tid];
        wgt[664 + tid] = w6[tid];
    } else {
        int u = tid - 128;
        if (u < 16)       wgt[u]            = w0[u];
        else if (u < 24)  wgt[u]            = b0[u - 16];
        else if (u < 32)  wgt[792 + (u-24)] = b1[u-24];
        else if (u < 40)  wgt[800 + (u-32)] = b2[u-32];
        else if (u < 48)  wgt[808 + (u-40)] = b3[u-40];
        else if (u < 56)  wgt[816 + (u-48)] = b4[u-48];
        else if (u < 64)  wgt[824 + (u-56)] = b5[u-56];
        else if (u < 72)  wgt[832 + (u-64)] = b6[u-64];
        else if (u < 88)  wgt[840 + (u-72)] = w7[u-72];
        else if (u == 88) wgt[856]          = b7[0];
    }
    __syncthreads();

    // ---- build register B-fragments + biases for layers 1..3 ----
    int g = lane >> 2, tq = lane & 3;
    uint32_t bf1[2], bf2[2], bf3[2];
    float bi1x, bi1y, bi2x, bi2y, bi3x, bi3y;
    {
        const float* W;
        W = wgt + 24;
        bf1[0] = pack_h2(W[g*16 + 4*tq],     W[g*16 + 4*tq + 2]);
        bf1[1] = pack_h2(W[g*16 + 4*tq + 1], W[g*16 + 4*tq + 3]);
        bi1x = wgt[792 + 2*tq]; bi1y = wgt[792 + 2*tq + 1];
        W = wgt + 152;
        bf2[0] = pack_h2(W[g*16 + 4*tq],     W[g*16 + 4*tq + 2]);
        bf2[1] = pack_h2(W[g*16 + 4*tq + 1], W[g*16 + 4*tq + 3]);
        bi2x = wgt[800 + 2*tq]; bi2y = wgt[800 + 2*tq + 1];
        W = wgt + 280;
        bf3[0] = pack_h2(W[g*16 + 4*tq],     W[g*16 + 4*tq + 2]);
        bf3[1] = pack_h2(W[g*16 + 4*tq + 1], W[g*16 + 4*tq + 3]);
        bi3x = wgt[808 + 2*tq]; bi3y = wgt[808 + 2*tq + 1];
    }

    uint32_t h0u = smem_u32(H0);
    uint32_t h1u = smem_u32(H1);
    uint32_t h2u = smem_u32(H2);

    // ---- L0: one thread per position, LDG direct from g_up, STS.128 out ----
    {
        float w0r[16], b0r[8];
        #pragma unroll
        for (int k = 0; k < 16; ++k) w0r[k] = wgt[k];
        #pragma unroll
        for (int k = 0; k < 8; ++k)  b0r[k] = wgt[16 + k];

        const __half2* gin = (const __half2*)(g_up + (size_t)b * LUP + (size_t)blk * 1536);
        #pragma unroll
        for (int it = 0; it < 3; ++it) {
            int p = it * 256 + tid;              // 0..767
            float2 u = __half22float2(gin[p]);
            float o[8];
            #pragma unroll
            for (int cc = 0; cc < 8; ++cc)
                o[cc] = lrelu(fmaf(w0r[2*cc], u.x, fmaf(w0r[2*cc + 1], u.y, b0r[cc])));
            uint4 pk = make_uint4(pack_h2(o[0], o[1]), pack_h2(o[2], o[3]),
                                  pack_h2(o[4], o[5]), pack_h2(o[6], o[7]));
            *(uint4*)((char*)H0 + p * 16) = pk;
        }
    }
    __syncthreads();

    // ---- L1: H0 (768 pos) -> H1 (384 pos), 24 chunks (ldmatrix A) ----
    #pragma unroll 1
    for (int ch = wid; ch < 24; ch += 8) {
        uint32_t a[4];
        ldsm_a(a, h0u, ch, lane);
        float d[4] = {bi1x, bi1y, bi1x, bi1y};
        mma_f16(d, a, bf1);
        uint32_t h01 = pack_h2(lrelu(d[0]), lrelu(d[1]));
        uint32_t h23 = pack_h2(lrelu(d[2]), lrelu(d[3]));
        char* ob = (char*)H1 + (ch * 16 + g) * 16 + tq * 4;
        *(uint32_t*)ob = h01;
        *(uint32_t*)(ob + 128) = h23;
    }
    __syncthreads();

    // ---- L2: H1 (384 pos) -> H2 (192 pos), 12 chunks (ldmatrix A) ----
    #pragma unroll 1
    for (int ch = wid; ch < 12; ch += 8) {
        uint32_t a[4];
        ldsm_a(a, h1u, ch, lane);
        float d[4] = {bi2x, bi2y, bi2x, bi2y};
        mma_f16(d, a, bf2);
        uint32_t h01 = pack_h2(lrelu(d[0]), lrelu(d[1]));
        uint32_t h23 = pack_h2(lrelu(d[2]), lrelu(d[3]));
        char* ob = (char*)H2 + (ch * 16 + g) * 16 + tq * 4;
        *(uint32_t*)ob = h01;
        *(uint32_t*)(ob + 128) = h23;
    }
    __syncthreads();

    // ---- L3: H2 (192 pos) -> F3 (96 pos, f32 out), 6 chunks (ldmatrix A) ----
    if (wid < 6) {
        int ch = wid;
        uint32_t a[4];
        ldsm_a(a, h2u, ch, lane);
        float d[4] = {bi3x, bi3y, bi3x, bi3y};
        mma_f16(d, a, bf3);
        float* ob = F3 + (ch * 16 + g) * 8 + 2 * tq;
        ob[0]  = lrelu(d[0]);  ob[1]      = lrelu(d[1]);
        ob[64] = lrelu(d[2]);  ob[64 + 1] = lrelu(d[3]);
    }
    __syncthreads();

    // ---- tail f32 scalar layers ----
    // L4: 384 outputs, strided
    for (int q = tid; q < 384; q += 256) {
        int p = q >> 3;
        int cc = q & 7;
        const float4* s4 = (const float4*)(F3 + 16 * p);
        const float4* Wc = (const float4*)(wgt + 408 + cc * 16);
        float4 wrA = Wc[0], wrB = Wc[1], wrC = Wc[2], wrD = Wc[3];
        float4 a0 = s4[0], a1 = s4[1], a2 = s4[2], a3 = s4[3];
        float acc = wgt[816 + cc];
        acc = fmaf(wrA.x, a0.x, acc); acc = fmaf(wrA.y, a2.x, acc);
        acc = fmaf(wrA.z, a0.y, acc); acc = fmaf(wrA.w, a2.y, acc);
        acc = fmaf(wrB.x, a0.z, acc); acc = fmaf(wrB.y, a2.z, acc);
        acc = fmaf(wrB.z, a0.w, acc); acc = fmaf(wrB.w, a2.w, acc);
        acc = fmaf(wrC.x, a1.x, acc); acc = fmaf(wrC.y, a3.x, acc);
        acc = fmaf(wrC.z, a1.y, acc); acc = fmaf(wrC.w, a3.y, acc);
        acc = fmaf(wrD.x, a1.z, acc); acc = fmaf(wrD.y, a3.z, acc);
        acc = fmaf(wrD.z, a1.w, acc); acc = fmaf(wrD.w, a3.w, acc);
        F4[p * 8 + cc] = lrelu(acc);
    }
    __syncthreads();
    // L5: 192 outputs
    if (tid < 192) {
        int p = tid >> 3;
        const float4* s4 = (const float4*)(F4 + 16 * p);
        const float4* Wc = (const float4*)(wgt + 536 + c * 16);
        float4 wrA = Wc[0], wrB = Wc[1], wrC = Wc[2], wrD = Wc[3];
        float4 a0 = s4[0], a1 = s4[1], a2 = s4[2], a3 = s4[3];
        float acc = wgt[824 + c];
        acc = fmaf(wrA.x, a0.x, acc); acc = fmaf(wrA.y, a2.x, acc);
        acc = fmaf(wrA.z, a0.y, acc); acc = fmaf(wrA.w, a2.y, acc);
        acc = fmaf(wrB.x, a0.z, acc); acc = fmaf(wrB.y, a2.z, acc);
        acc = fmaf(wrB.z, a0.w, acc); acc = fmaf(wrB.w, a2.w, acc);
        acc = fmaf(wrC.x, a1.x, acc); acc = fmaf(wrC.y, a3.x, acc);
        acc = fmaf(wrC.z, a1.y, acc); acc = fmaf(wrC.w, a3.y, acc);
        acc = fmaf(wrD.x, a1.z, acc); acc = fmaf(wrD.y, a3.z, acc);
        acc = fmaf(wrD.z, a1.w, acc); acc = fmaf(wrD.w, a3.w, acc);
        F5[p * 8 + c] = lrelu(acc);
    }
    __syncthreads();
    // L6: 96 outputs
    if (tid < 96) {
        int p = tid >> 3;
        const float4* s4 = (const float4*)(F5 + 16 * p);
        const float4* Wc = (const float4*)(wgt + 664 + c * 16);
        float4 wrA = Wc[0], wrB = Wc[1], wrC = Wc[2], wrD = Wc[3];
        float4 a0 = s4[0], a1 = s4[1], a2 = s4[2], a3 = s4[3];
        float acc = wgt[832 + c];
        acc = fmaf(wrA.x, a0.x, acc); acc = fmaf(wrA.y, a2.x, acc);
        acc = fmaf(wrA.z, a0.y, acc); acc = fmaf(wrA.w, a2.y, acc);
        acc = fmaf(wrB.x, a0.z, acc); acc = fmaf(wrB.y, a2.z, acc);
        acc = fmaf(wrB.z, a0.w, acc); acc = fmaf(wrB.w, a2.w, acc);
        acc = fmaf(wrC.x, a1.x, acc); acc = fmaf(wrC.y, a3.x, acc);
        acc = fmaf(wrC.z, a1.y, acc); acc = fmaf(wrC.w, a3.y, acc);
        acc = fmaf(wrD.x, a1.z, acc); acc = fmaf(wrD.y, a3.z, acc);
        acc = fmaf(wrD.z, a1.w, acc); acc = fmaf(wrD.w, a3.w, acc);
        F6[p * 8 + c] = lrelu(acc);
    }
    __syncthreads();
    // L7: 6 outputs, no activation
    if (tid < 6) {
        const float* s0 = F6 + 16 * tid;
        const float4* Wc = (const float4*)(wgt + 840);
        float4 wa = Wc[0], wb = Wc[1], wc2 = Wc[2], wd = Wc[3];
        float acc = wgt[856];
        acc = fmaf(wa.x,  s0[0], acc); acc = fmaf(wa.y,  s0[8],  acc);
        acc = fmaf(wa.z,  s0[1], acc); acc = fmaf(wa.w,  s0[9],  acc);
        acc = fmaf(wb.x,  s0[2], acc); acc = fmaf(wb.y,  s0[10], acc);
        acc = fmaf(wb.z,  s0[3], acc); acc = fmaf(wb.w,  s0[11], acc);
        acc = fmaf(wc2.x, s0[4], acc); acc = fmaf(wc2.y, s0[12], acc);
        acc = fmaf(wc2.z, s0[5], acc); acc = fmaf(wc2.w, s0[13], acc);
        acc = fmaf(wd.x,  s0[6], acc); acc = fmaf(wd.y,  s0[14], acc);
        acc = fmaf(wd.z,  s0[7], acc); acc = fmaf(wd.w,  s0[15], acc);
        out[b * NOUT + blk * 6 + tid] = acc;
    }
}

// ---------------------------------------------------------------------------
extern "C" void kernel_launch(void* const* d_in, const int* in_sizes, int n_in,
                              void* d_out, int out_size) {
    const float* x = (const float*)d_in[0];
    const float* w[8];
    const float* bb[8];
    for (int i = 0; i < 8; ++i) {
        w[i]  = (const float*)d_in[1 + 2 * i];
        bb[i] = (const float*)d_in[2 + 2 * i];
    }
    float* out = (float*)d_out;

    cudaFuncSetAttribute(dist_kernel,
                         cudaFuncAttributeMaxDynamicSharedMemorySize, DIST_SMEM);

    dist_kernel<<<dim3(36, NB), 256, DIST_SMEM>>>(x);
    conv_kernel<<<dim3(341, NB), 256>>>(
        w[0], bb[0], w[1], bb[1], w[2], bb[2], w[3], bb[3],
        w[4], bb[4], w[5], bb[5], w[6], bb[6], w[7], bb[7], out);
}

// round 17
// speedup vs baseline: 1.2615x; 1.0701x over previous
#include <cuda_runtime.h>
#include <cuda_fp16.h>
#include <math.h>
#include <stdint.h>

#define T 1024
#define C 128
#define NB 16
#define LUP 523776          // T*(T-1)/2
#define NOUT 2046           // LUP / 256
#define LEAK 0.2f

// ---------------------------------------------------------------------------
// Device globals (scratch)
// ---------------------------------------------------------------------------
__device__ __half g_up[(size_t)NB * LUP];  // packed upper-triangle distances (fp16)

// ---------------------------------------------------------------------------
// Helpers
// ---------------------------------------------------------------------------
__device__ __forceinline__ uint32_t smem_u32(const void* p) {
    uint32_t a;
    asm("{ .reg .u64 t; cvta.to.shared.u64 t, %1; cvt.u32.u64 %0, t; }"
        : "=r"(a) : "l"(p));
    return a;
}

__device__ __forceinline__ uint32_t to_tf32(float f) {
    uint32_t r;
    asm("cvt.rna.tf32.f32 %0, %1;" : "=r"(r) : "f"(f));
    return r;
}

__device__ __forceinline__ void mma_tf32(float* d, const uint32_t* a, const uint32_t* b) {
    asm volatile(
        "mma.sync.aligned.m16n8k8.row.col.f32.tf32.tf32.f32 "
        "{%0,%1,%2,%3}, {%4,%5,%6,%7}, {%8,%9}, {%0,%1,%2,%3};"
        : "+f"(d[0]), "+f"(d[1]), "+f"(d[2]), "+f"(d[3])
        : "r"(a[0]), "r"(a[1]), "r"(a[2]), "r"(a[3]),
          "r"(b[0]), "r"(b[1]));
}

__device__ __forceinline__ void mma_f16(float* d, const uint32_t* a, const uint32_t* b) {
    asm volatile(
        "mma.sync.aligned.m16n8k16.row.col.f32.f16.f16.f32 "
        "{%0,%1,%2,%3}, {%4,%5,%6,%7}, {%8,%9}, {%0,%1,%2,%3};"
        : "+f"(d[0]), "+f"(d[1]), "+f"(d[2]), "+f"(d[3])
        : "r"(a[0]), "r"(a[1]), "r"(a[2]), "r"(a[3]),
          "r"(b[0]), "r"(b[1]));
}

// warp-collective: load the 16x16 f16 A-tile of chunk ch from a 32B/row buffer
__device__ __forceinline__ void ldsm_a(uint32_t* a, uint32_t base, int ch, int lane) {
    int mat = lane >> 3, r = lane & 7;
    uint32_t addr = base + (uint32_t)((ch * 16 + (mat & 1) * 8 + r) * 32 + (mat >> 1) * 16);
    asm volatile(
        "ldmatrix.sync.aligned.m8n8.x4.shared.b16 {%0,%1,%2,%3}, [%4];"
        : "=r"(a[0]), "=r"(a[1]), "=r"(a[2]), "=r"(a[3])
        : "r"(addr));
}

__device__ __forceinline__ float lrelu(float v) {
    return fmaxf(v, LEAK * v);
}

__device__ __forceinline__ float fsqrt_approx(float v) {
    float r;
    asm("sqrt.approx.f32 %0, %1;" : "=f"(r) : "f"(v));
    return r;
}

__device__ __forceinline__ uint32_t pack_h2(float x, float y) {
    __half2 h = __floats2half2_rn(x, y);
    return *(uint32_t*)&h;
}

// ---------------------------------------------------------------------------
// Kernel 1 (v2): tf32 mma.sync Gram tiles -> packed fp16 sqrt distances.
// TWO-PHASE K-SPLIT: tiles are 128 x 64 tf32 (stride 68), smem 69.6KB
// -> 2 CTAs/SM (was 135KB @ 1 CTA/SM). Mainloop: {load k-half, sxx add,
// mma} x 2. Epilogue identical to the 94.3us build.
// ---------------------------------------------------------------------------
#define AS_STRIDE 68
#define AS_BYTES  (128 * AS_STRIDE * 4)       // 34816
#define DIST_SMEM (2 * AS_BYTES + 1024)       // 70656 (+ sxx[256])
#define HS_STRIDE 130

__global__ __launch_bounds__(256) void dist_kernel(const float* __restrict__ x) {
    extern __shared__ __align__(16) unsigned char sm[];
    uint32_t* As = (uint32_t*)sm;
    uint32_t* Bs = (uint32_t*)(sm + AS_BYTES);
    float* sxx   = (float*)(sm + 2 * AS_BYTES);

    int tid = threadIdx.x;
    int wid = tid >> 5;
    int lane = tid & 31;
    int grp = lane >> 2;
    int tg  = lane & 3;

    int b = blockIdx.y;
    int t = blockIdx.x;
    int ti = 0, rem = t;
    while (rem >= 8 - ti) { rem -= 8 - ti; ++ti; }
    int tj = ti + rem;
    int i0 = ti * 128, j0 = tj * 128;

    const float* xb = x + (size_t)b * T * C;

    int warp_m = (wid >> 2) * 64;
    int warp_n = (wid & 3) * 32;

    float acc[4][4][4];
    #pragma unroll
    for (int e = 0; e < 4; ++e)
        #pragma unroll
        for (int f = 0; f < 4; ++f)
            #pragma unroll
            for (int q = 0; q < 4; ++q) acc[e][f][q] = 0.0f;

    int abase = (warp_m + grp) * AS_STRIDE + tg;
    int bbase = (warp_n + grp) * AS_STRIDE + tg;

    float sxx_acc = 0.0f;

    #pragma unroll 1
    for (int ph = 0; ph < 2; ++ph) {
        int k0 = ph * 64;

        // ---- load k-half: 128 rows x 64 cols per tile (8 x 256 float4) ----
        #pragma unroll
        for (int it = 0; it < 8; ++it) {
            int f4 = it * 256 + tid;          // 0..2047
            int row = f4 >> 4, c4 = f4 & 15;
            float4 va = *(const float4*)(xb + (size_t)(i0 + row) * C + k0 + c4 * 4);
            uint4 ta = make_uint4(to_tf32(va.x), to_tf32(va.y), to_tf32(va.z), to_tf32(va.w));
            *(uint4*)&As[row * AS_STRIDE + c4 * 4] = ta;
            float4 vb = *(const float4*)(xb + (size_t)(j0 + row) * C + k0 + c4 * 4);
            uint4 tb = make_uint4(to_tf32(vb.x), to_tf32(vb.y), to_tf32(vb.z), to_tf32(vb.w));
            *(uint4*)&Bs[row * AS_STRIDE + c4 * 4] = tb;
        }
        __syncthreads();

        // ---- sxx partial for this k-half ----
        {
            int r = tid & 127;
            const uint32_t* Row = ((tid < 128) ? As : Bs) + r * AS_STRIDE;
            float s = 0.0f;
            #pragma unroll
            for (int k = 0; k < 64; k += 4) {
                float4 v = *(const float4*)&Row[k];
                s = fmaf(v.x, v.x, s); s = fmaf(v.y, v.y, s);
                s = fmaf(v.z, v.z, s); s = fmaf(v.w, v.w, s);
            }
            sxx_acc += s;
            sxx[tid] = sxx_acc;
        }

        // ---- mma over this k-half ----
        #pragma unroll 2
        for (int kb = 0; kb < 64; kb += 8) {
            uint32_t a[4][4], bf[4][2];
            #pragma unroll
            for (int e = 0; e < 4; ++e) {
                int r = abase + 16 * e * AS_STRIDE + kb;
                a[e][0] = As[r];
                a[e][1] = As[r + 8 * AS_STRIDE];
                a[e][2] = As[r + 4];
                a[e][3] = As[r + 8 * AS_STRIDE + 4];
            }
            #pragma unroll
            for (int f = 0; f < 4; ++f) {
                int r = bbase + 8 * f * AS_STRIDE + kb;
                bf[f][0] = Bs[r];
                bf[f][1] = Bs[r + 4];
            }
            #pragma unroll
            for (int e = 0; e < 4; ++e)
                #pragma unroll
                for (int f = 0; f < 4; ++f)
                    mma_tf32(acc[e][f], a[e], bf[f]);
        }
        __syncthreads();   // all reads done before next phase load / epilogue reuse
    }

    float xi[4][2], xj[4][2];
    #pragma unroll
    for (int e = 0; e < 4; ++e) {
        int il = warp_m + 16 * e + grp;
        xi[e][0] = sxx[il];
        xi[e][1] = sxx[il + 8];
    }
    #pragma unroll
    for (int f = 0; f < 4; ++f) {
        int jl = warp_n + 8 * f + 2 * tg;
        xj[f][0] = sxx[128 + jl];
        xj[f][1] = sxx[128 + jl + 1];
    }

    __half* S = (__half*)sm;   // 128 x stride-130 half staging (33.3KB < As)

    #pragma unroll
    for (int e = 0; e < 4; ++e) {
        int il = warp_m + 16 * e + grp;
        #pragma unroll
        for (int f = 0; f < 4; ++f) {
            int jl = warp_n + 8 * f + 2 * tg;
            float d00 = fmaf(-2.0f, acc[e][f][0], xi[e][0] + xj[f][0]);
            float d01 = fmaf(-2.0f, acc[e][f][1], xi[e][0] + xj[f][1]);
            float d10 = fmaf(-2.0f, acc[e][f][2], xi[e][1] + xj[f][0]);
            float d11 = fmaf(-2.0f, acc[e][f][3], xi[e][1] + xj[f][1]);
            float s00 = fsqrt_approx(fmaxf(d00, 0.0f));
            float s01 = fsqrt_approx(fmaxf(d01, 0.0f));
            float s10 = fsqrt_approx(fmaxf(d10, 0.0f));
            float s11 = fsqrt_approx(fmaxf(d11, 0.0f));
            *(__half2*)&S[il * HS_STRIDE + jl]       = __floats2half2_rn(s00, s01);
            *(__half2*)&S[(il + 8) * HS_STRIDE + jl] = __floats2half2_rn(s10, s11);
        }
    }
    __syncthreads();

    {
        long bbase2 = (long)b * LUP;
        #pragma unroll
        for (int q = tid; q < 128 * 128; q += 256) {
            int m = q >> 7, jj = q & 127;
            int i2 = i0 + m, j2 = j0 + jj;
            if (j2 > i2) {
                long ro = (long)i2 * (2 * T - 1 - i2) / 2 - i2 - 1;
                g_up[bbase2 + ro + j2] = S[m * HS_STRIDE + jj];
            }
        }
    }
}

// ---------------------------------------------------------------------------
// Kernel 2 (v6.4): HMMA conv with ldmatrix A loads — verbatim from the
// 94.3us round-16 build.
// ---------------------------------------------------------------------------
__global__ __launch_bounds__(256) void conv_kernel(
    const float* __restrict__ w0, const float* __restrict__ b0,
    const float* __restrict__ w1, const float* __restrict__ b1,
    const float* __restrict__ w2, const float* __restrict__ b2,
    const float* __restrict__ w3, const float* __restrict__ b3,
    const float* __restrict__ w4, const float* __restrict__ b4,
    const float* __restrict__ w5, const float* __restrict__ b5,
    const float* __restrict__ w6, const float* __restrict__ b6,
    const float* __restrict__ w7, const float* __restrict__ b7,
    float* __restrict__ out)
{
    __shared__ float  wgt[860];
    __shared__ __align__(16) __half H0[6144];
    __shared__ __align__(16) __half H1[3072];
    __shared__ __align__(16) __half H2[1536];
    __shared__ float  F3[768];
    __shared__ float  F4[384];
    __shared__ float  F5[192];
    __shared__ float  F6[96];

    int tid = threadIdx.x;
    int wid = tid >> 5;
    int lane = tid & 31;
    int c   = tid & 7;
    int b   = blockIdx.y;
    int blk = blockIdx.x;        // 0..340

    if (tid < 128) {
        wgt[ 24 + tid] = w1[tid];
        wgt[152 + tid] = w2[tid];
        wgt[280 + tid] = w3[tid];
        wgt[408 + tid] = w4[tid];
        wgt[536 + tid] = w5[tid];
        wgt[664 + tid] = w6[tid];
    } else {
        int u = tid - 128;
        if (u < 16)       wgt[u]            = w0[u];
        else if (u < 24)  wgt[u]            = b0[u - 16];
        else if (u < 32)  wgt[792 + (u-24)] = b1[u-24];
        else if (u < 40)  wgt[800 + (u-32)] = b2[u-32];
        else if (u < 48)  wgt[808 + (u-40)] = b3[u-40];
        else if (u < 56)  wgt[816 + (u-48)] = b4[u-48];
        else if (u < 64)  wgt[824 + (u-56)] = b5[u-56];
        else if (u < 72)  wgt[832 + (u-64)] = b6[u-64];
        else if (u < 88)  wgt[840 + (u-72)] = w7[u-72];
        else if (u == 88) wgt[856]          = b7[0];
    }
    __syncthreads();

    int g = lane >> 2, tq = lane & 3;
    uint32_t bf1[2], bf2[2], bf3[2];
    float bi1x, bi1y, bi2x, bi2y, bi3x, bi3y;
    {
        const float* W;
        W = wgt + 24;
        bf1[0] = pack_h2(W[g*16 + 4*tq],     W[g*16 + 4*tq + 2]);
        bf1[1] = pack_h2(W[g*16 + 4*tq + 1], W[g*16 + 4*tq + 3]);
        bi1x = wgt[792 + 2*tq]; bi1y = wgt[792 + 2*tq + 1];
        W = wgt + 152;
        bf2[0] = pack_h2(W[g*16 + 4*tq],     W[g*16 + 4*tq + 2]);
        bf2[1] = pack_h2(W[g*16 + 4*tq + 1], W[g*16 + 4*tq + 3]);
        bi2x = wgt[800 + 2*tq]; bi2y = wgt[800 + 2*tq + 1];
        W = wgt + 280;
        bf3[0] = pack_h2(W[g*16 + 4*tq],     W[g*16 + 4*tq + 2]);
        bf3[1] = pack_h2(W[g*16 + 4*tq + 1], W[g*16 + 4*tq + 3]);
        bi3x = wgt[808 + 2*tq]; bi3y = wgt[808 + 2*tq + 1];
    }

    uint32_t h0u = smem_u32(H0);
    uint32_t h1u = smem_u32(H1);
    uint32_t h2u = smem_u32(H2);

    {
        float w0r[16], b0r[8];
        #pragma unroll
        for (int k = 0; k < 16; ++k) w0r[k] = wgt[k];
        #pragma unroll
        for (int k = 0; k < 8; ++k)  b0r[k] = wgt[16 + k];

        const __half2* gin = (const __half2*)(g_up + (size_t)b * LUP + (size_t)blk * 1536);
        #pragma unroll
        for (int it = 0; it < 3; ++it) {
            int p = it * 256 + tid;
            float2 u = __half22float2(gin[p]);
            float o[8];
            #pragma unroll
            for (int cc = 0; cc < 8; ++cc)
                o[cc] = lrelu(fmaf(w0r[2*cc], u.x, fmaf(w0r[2*cc + 1], u.y, b0r[cc])));
            uint4 pk = make_uint4(pack_h2(o[0], o[1]), pack_h2(o[2], o[3]),
                                  pack_h2(o[4], o[5]), pack_h2(o[6], o[7]));
            *(uint4*)((char*)H0 + p * 16) = pk;
        }
    }
    __syncthreads();

    #pragma unroll 1
    for (int ch = wid; ch < 24; ch += 8) {
        uint32_t a[4];
        ldsm_a(a, h0u, ch, lane);
        float d[4] = {bi1x, bi1y, bi1x, bi1y};
        mma_f16(d, a, bf1);
        uint32_t h01 = pack_h2(lrelu(d[0]), lrelu(d[1]));
        uint32_t h23 = pack_h2(lrelu(d[2]), lrelu(d[3]));
        char* ob = (char*)H1 + (ch * 16 + g) * 16 + tq * 4;
        *(uint32_t*)ob = h01;
        *(uint32_t*)(ob + 128) = h23;
    }
    __syncthreads();

    #pragma unroll 1
    for (int ch = wid; ch < 12; ch += 8) {
        uint32_t a[4];
        ldsm_a(a, h1u, ch, lane);
        float d[4] = {bi2x, bi2y, bi2x, bi2y};
        mma_f16(d, a, bf2);
        uint32_t h01 = pack_h2(lrelu(d[0]), lrelu(d[1]));
        uint32_t h23 = pack_h2(lrelu(d[2]), lrelu(d[3]));
        char* ob = (char*)H2 + (ch * 16 + g) * 16 + tq * 4;
        *(uint32_t*)ob = h01;
        *(uint32_t*)(ob + 128) = h23;
    }
    __syncthreads();

    if (wid < 6) {
        int ch = wid;
        uint32_t a[4];
        ldsm_a(a, h2u, ch, lane);
        float d[4] = {bi3x, bi3y, bi3x, bi3y};
        mma_f16(d, a, bf3);
        float* ob = F3 + (ch * 16 + g) * 8 + 2 * tq;
        ob[0]  = lrelu(d[0]);  ob[1]      = lrelu(d[1]);
        ob[64] = lrelu(d[2]);  ob[64 + 1] = lrelu(d[3]);
    }
    __syncthreads();

    for (int q = tid; q < 384; q += 256) {
        int p = q >> 3;
        int cc = q & 7;
        const float4* s4 = (const float4*)(F3 + 16 * p);
        const float4* Wc = (const float4*)(wgt + 408 + cc * 16);
        float4 wrA = Wc[0], wrB = Wc[1], wrC = Wc[2], wrD = Wc[3];
        float4 a0 = s4[0], a1 = s4[1], a2 = s4[2], a3 = s4[3];
        float acc = wgt[816 + cc];
        acc = fmaf(wrA.x, a0.x, acc); acc = fmaf(wrA.y, a2.x, acc);
        acc = fmaf(wrA.z, a0.y, acc); acc = fmaf(wrA.w, a2.y, acc);
        acc = fmaf(wrB.x, a0.z, acc); acc = fmaf(wrB.y, a2.z, acc);
        acc = fmaf(wrB.z, a0.w, acc); acc = fmaf(wrB.w, a2.w, acc);
        acc = fmaf(wrC.x, a1.x, acc); acc = fmaf(wrC.y, a3.x, acc);
        acc = fmaf(wrC.z, a1.y, acc); acc = fmaf(wrC.w, a3.y, acc);
        acc = fmaf(wrD.x, a1.z, acc); acc = fmaf(wrD.y, a3.z, acc);
        acc = fmaf(wrD.z, a1.w, acc); acc = fmaf(wrD.w, a3.w, acc);
        F4[p * 8 + cc] = lrelu(acc);
    }
    __syncthreads();
    if (tid < 192) {
        int p = tid >> 3;
        const float4* s4 = (const float4*)(F4 + 16 * p);
        const float4* Wc = (const float4*)(wgt + 536 + c * 16);
        float4 wrA = Wc[0], wrB = Wc[1], wrC = Wc[2], wrD = Wc[3];
        float4 a0 = s4[0], a1 = s4[1], a2 = s4[2], a3 = s4[3];
        float acc = wgt[824 + c];
        acc = fmaf(wrA.x, a0.x, acc); acc = fmaf(wrA.y, a2.x, acc);
        acc = fmaf(wrA.z, a0.y, acc); acc = fmaf(wrA.w, a2.y, acc);
        acc = fmaf(wrB.x, a0.z, acc); acc = fmaf(wrB.y, a2.z, acc);
        acc = fmaf(wrB.z, a0.w, acc); acc = fmaf(wrB.w, a2.w, acc);
        acc = fmaf(wrC.x, a1.x, acc); acc = fmaf(wrC.y, a3.x, acc);
        acc = fmaf(wrC.z, a1.y, acc); acc = fmaf(wrC.w, a3.y, acc);
        acc = fmaf(wrD.x, a1.z, acc); acc = fmaf(wrD.y, a3.z, acc);
        acc = fmaf(wrD.z, a1.w, acc); acc = fmaf(wrD.w, a3.w, acc);
        F5[p * 8 + c] = lrelu(acc);
    }
    __syncthreads();
    if (tid < 96) {
        int p = tid >> 3;
        const float4* s4 = (const float4*)(F5 + 16 * p);
        const float4* Wc = (const float4*)(wgt + 664 + c * 16);
        float4 wrA = Wc[0], wrB = Wc[1], wrC = Wc[2], wrD = Wc[3];
        float4 a0 = s4[0], a1 = s4[1], a2 = s4[2], a3 = s4[3];
        float acc = wgt[832 + c];
        acc = fmaf(wrA.x, a0.x, acc); acc = fmaf(wrA.y, a2.x, acc);
        acc = fmaf(wrA.z, a0.y, acc); acc = fmaf(wrA.w, a2.y, acc);
        acc = fmaf(wrB.x, a0.z, acc); acc = fmaf(wrB.y, a2.z, acc);
        acc = fmaf(wrB.z, a0.w, acc); acc = fmaf(wrB.w, a2.w, acc);
        acc = fmaf(wrC.x, a1.x, acc); acc = fmaf(wrC.y, a3.x, acc);
        acc = fmaf(wrC.z, a1.y, acc); acc = fmaf(wrC.w, a3.y, acc);
        acc = fmaf(wrD.x, a1.z, acc); acc = fmaf(wrD.y, a3.z, acc);
        acc = fmaf(wrD.z, a1.w, acc); acc = fmaf(wrD.w, a3.w, acc);
        F6[p * 8 + c] = lrelu(acc);
    }
    __syncthreads();
    if (tid < 6) {
        const float* s0 = F6 + 16 * tid;
        const float4* Wc = (const float4*)(wgt + 840);
        float4 wa = Wc[0], wb = Wc[1], wc2 = Wc[2], wd = Wc[3];
        float acc = wgt[856];
        acc = fmaf(wa.x,  s0[0], acc); acc = fmaf(wa.y,  s0[8],  acc);
        acc = fmaf(wa.z,  s0[1], acc); acc = fmaf(wa.w,  s0[9],  acc);
        acc = fmaf(wb.x,  s0[2], acc); acc = fmaf(wb.y,  s0[10], acc);
        acc = fmaf(wb.z,  s0[3], acc); acc = fmaf(wb.w,  s0[11], acc);
        acc = fmaf(wc2.x, s0[4], acc); acc = fmaf(wc2.y, s0[12], acc);
        acc = fmaf(wc2.z, s0[5], acc); acc = fmaf(wc2.w, s0[13], acc);
        acc = fmaf(wd.x,  s0[6], acc); acc = fmaf(wd.y,  s0[14], acc);
        acc = fmaf(wd.z,  s0[7], acc); acc = fmaf(wd.w,  s0[15], acc);
        out[b * NOUT + blk * 6 + tid] = acc;
    }
}

// ---------------------------------------------------------------------------
extern "C" void kernel_launch(void* const* d_in, const int* in_sizes, int n_in,
                              void* d_out, int out_size) {
    const float* x = (const float*)d_in[0];
    const float* w[8];
    const float* bb[8];
    for (int i = 0; i < 8; ++i) {
        w[i]  = (const float*)d_in[1 + 2 * i];
        bb[i] = (const float*)d_in[2 + 2 * i];
    }
    float* out = (float*)d_out;

    cudaFuncSetAttribute(dist_kernel,
                         cudaFuncAttributeMaxDynamicSharedMemorySize, DIST_SMEM);

    dist_kernel<<<dim3(36, NB), 256, DIST_SMEM>>>(x);
    conv_kernel<<<dim3(341, NB), 256>>>(
        w[0], bb[0], w[1], bb[1], w[2], bb[2], w[3], bb[3],
        w[4], bb[4], w[5], bb[5], w[6], bb[6], w[7], bb[7], out);
}